// round 7
// baseline (speedup 1.0000x reference)
#include <cuda_runtime.h>
#include <math.h>
#include <stdint.h>

// Problem dims (fixed by the reference)
#define BB 2
#define TT 2048
#define CC 1024
#define NH 16
#define HD 64
#define MROWS (BB*TT)   // 4096

// Scratch (allocation-free rule: __device__ globals)
__device__ float g_qkv[(size_t)BB * TT * 3 * CC];  // [B,T,3C] (tf32-rounded)
__device__ float g_y[(size_t)MROWS * CC];          // attention output (tf32-rounded)
__device__ float g_x[(size_t)MROWS * CC];          // tf32-rounded x
__device__ float g_wa[(size_t)CC * 3 * CC];        // tf32-rounded w_attn
__device__ float g_wp[(size_t)CC * CC];            // tf32-rounded w_proj

// ---------------------------------------------------------------------------
__device__ __forceinline__ float to_tf32(float f) {
    uint32_t r;
    asm("cvt.rna.tf32.f32 %0, %1;" : "=r"(r) : "f"(f));
    return __uint_as_float(r);
}

// mma.sync m16n8k8 tf32 (sm_80+ path; supported on plain sm_100 target)
__device__ __forceinline__ void mma_tf32(float c[4], const uint32_t a[4], const uint32_t b[2]) {
    asm volatile(
        "mma.sync.aligned.m16n8k8.row.col.f32.tf32.tf32.f32 "
        "{%0,%1,%2,%3}, {%4,%5,%6,%7}, {%8,%9}, {%0,%1,%2,%3};"
        : "+f"(c[0]), "+f"(c[1]), "+f"(c[2]), "+f"(c[3])
        : "r"(a[0]), "r"(a[1]), "r"(a[2]), "r"(a[3]), "r"(b[0]), "r"(b[1]));
}

__device__ __forceinline__ uint32_t smem_u32(const void* p) {
    uint32_t a;
    asm("{ .reg .u64 t; cvta.to.shared.u64 t, %1; cvt.u32.u64 %0, t; }" : "=r"(a) : "l"(p));
    return a;
}
__device__ __forceinline__ void cp_async16(uint32_t dst, const void* src) {
    asm volatile("cp.async.cg.shared.global [%0], [%1], 16;" :: "r"(dst), "l"(src) : "memory");
}
__device__ __forceinline__ void cp_commit() {
    asm volatile("cp.async.commit_group;" ::: "memory");
}
template <int N>
__device__ __forceinline__ void cp_wait() {
    asm volatile("cp.async.wait_group %0;" :: "n"(N) : "memory");
}

// ---------------------------------------------------------------------------
// fused tf32(rna) rounding of x, w_attn, w_proj in one launch
// ---------------------------------------------------------------------------
#define N4_X  (MROWS * CC / 4)          // 1048576
#define N4_WA (CC * 3 * CC / 4)         // 786432
#define N4_WP (CC * CC / 4)             // 262144

__global__ void round_all(const float* __restrict__ x,  float* __restrict__ xo,
                          const float* __restrict__ wa, float* __restrict__ wao,
                          const float* __restrict__ wp, float* __restrict__ wpo) {
    const int total = N4_X + N4_WA + N4_WP;
    int i = blockIdx.x * blockDim.x + threadIdx.x;
    int stride = gridDim.x * blockDim.x;
    for (; i < total; i += stride) {
        const float4* src;
        float4* dst;
        int idx;
        if (i < N4_X)               { src = (const float4*)x;  dst = (float4*)xo;  idx = i; }
        else if (i < N4_X + N4_WA)  { src = (const float4*)wa; dst = (float4*)wao; idx = i - N4_X; }
        else                        { src = (const float4*)wp; dst = (float4*)wpo; idx = i - N4_X - N4_WA; }
        float4 v = src[idx];
        v.x = to_tf32(v.x); v.y = to_tf32(v.y);
        v.z = to_tf32(v.z); v.w = to_tf32(v.w);
        dst[idx] = v;
    }
}

// ---------------------------------------------------------------------------
// tf32 mma.sync GEMM v3: C[M,N] = A[M,K] @ B[K,N] + bias[N]
// CTA 128x128, BK=32, 256 threads (8 warps, 2x4), warp tile 64x32.
// cp.async 3-stage pipeline; sA [128][36], sB [32][136] (conflict-free frags).
// round_out != 0 -> store outputs tf32(rna)-rounded (for downstream mma use).
// ---------------------------------------------------------------------------
#define SA_LD 36
#define SB_LD 136
#define STAGE_F 8960           // floats per stage (35840 B)
#define SA_F 4608              // floats in sA (18432 B)

__global__ __launch_bounds__(256, 2)
void gemm_mma(const float* __restrict__ A, const float* __restrict__ B,
              const float* __restrict__ bias, float* __restrict__ C,
              int M, int N, int K, int round_out)
{
    extern __shared__ float sm[];
    const uint32_t sbase = smem_u32(sm);
    const int tid  = threadIdx.x;
    const int lane = tid & 31;
    const int wid  = tid >> 5;
    const int wm   = wid & 1;        // 0..1 (64-row block)
    const int wn   = wid >> 1;       // 0..3 (32-col block)
    const int brow = blockIdx.y, bcol = blockIdx.x;

    const float* Ag = A + (size_t)(brow * 128) * K;
    const float* Bg = B + (size_t)bcol * 128;

    const int NT = K / 32;

    auto issue_stage = [&](int kt, int s) {
        const uint32_t stage_b = (uint32_t)s * (STAGE_F * 4);
        #pragma unroll
        for (int i = 0; i < 4; i++) {
            int id  = tid + i * 256;
            int row = id >> 3, c4 = (id & 7) << 2;
            uint32_t dst = sbase + stage_b + (uint32_t)(row * SA_LD + c4) * 4u;
            cp_async16(dst, Ag + (size_t)row * K + kt * 32 + c4);
        }
        #pragma unroll
        for (int i = 0; i < 4; i++) {
            int id = tid + i * 256;
            int k  = id >> 5, n4 = (id & 31) << 2;
            uint32_t dst = sbase + stage_b + (uint32_t)(SA_F + k * SB_LD + n4) * 4u;
            cp_async16(dst, Bg + (size_t)(kt * 32 + k) * N + n4);
        }
        cp_commit();
    };

    float acc[4][4][4];
    #pragma unroll
    for (int i = 0; i < 4; i++)
        #pragma unroll
        for (int j = 0; j < 4; j++)
            #pragma unroll
            for (int e = 0; e < 4; e++) acc[i][j][e] = 0.f;

    issue_stage(0, 0);
    issue_stage(1, 1);

    const int r4 = lane >> 2;
    const int c4 = lane & 3;

    for (int kt = 0; kt < NT; kt++) {
        if (kt + 2 < NT) cp_wait<1>(); else cp_wait<0>();
        __syncthreads();
        if (kt + 2 < NT) issue_stage(kt + 2, (kt + 2) % 3);

        const float* sA = sm + (kt % 3) * STAGE_F;
        const float* sB = sA + SA_F;

        #pragma unroll
        for (int ks = 0; ks < 4; ks++) {
            uint32_t a[4][4], b[4][2];
            #pragma unroll
            for (int i = 0; i < 4; i++) {
                const float* p = sA + (wm * 64 + i * 16 + r4) * SA_LD + ks * 8 + c4;
                a[i][0] = __float_as_uint(p[0]);
                a[i][1] = __float_as_uint(p[8 * SA_LD]);
                a[i][2] = __float_as_uint(p[4]);
                a[i][3] = __float_as_uint(p[8 * SA_LD + 4]);
            }
            #pragma unroll
            for (int j = 0; j < 4; j++) {
                const float* p = sB + (ks * 8 + c4) * SB_LD + wn * 32 + j * 8 + r4;
                b[j][0] = __float_as_uint(p[0]);
                b[j][1] = __float_as_uint(p[4 * SB_LD]);
            }
            #pragma unroll
            for (int i = 0; i < 4; i++)
                #pragma unroll
                for (int j = 0; j < 4; j++)
                    mma_tf32(acc[i][j], a[i], b[j]);
        }
        __syncthreads();
    }

    #pragma unroll
    for (int i = 0; i < 4; i++) {
        const int gm0 = brow * 128 + wm * 64 + i * 16 + r4;
        #pragma unroll
        for (int j = 0; j < 4; j++) {
            const int gn = bcol * 128 + wn * 32 + j * 8 + c4 * 2;
            const float b0 = bias[gn], b1 = bias[gn + 1];
            float v00 = acc[i][j][0] + b0, v01 = acc[i][j][1] + b1;
            float v10 = acc[i][j][2] + b0, v11 = acc[i][j][3] + b1;
            if (round_out) {
                v00 = to_tf32(v00); v01 = to_tf32(v01);
                v10 = to_tf32(v10); v11 = to_tf32(v11);
            }
            *(float2*)(C + (size_t)gm0 * N + gn)       = make_float2(v00, v01);
            *(float2*)(C + (size_t)(gm0 + 8) * N + gn) = make_float2(v10, v11);
        }
    }
}

// ---------------------------------------------------------------------------
// Flash attention v2: mma.sync tf32, online softmax in fragment layout.
// Grid (32, NH, BB), 128 threads (4 warps), BQ=64 (warp m16), BKV=64, D=64.
// SMEM (floats): Q[64][68] @0, P[64][68] @4352, K double [64][68] @8704,
//                V double [64][72] @17408; total 26624 f = 106496 B; 2 CTA/SM.
// ---------------------------------------------------------------------------
#define FQ_OFF 0
#define FP_OFF 4352
#define FK_OFF 8704
#define FV_OFF 17408
#define FLASH_SMEM_B (26624 * 4)

__global__ __launch_bounds__(128, 2)
void flash_mma(const float* __restrict__ qkv, float* __restrict__ y)
{
    extern __shared__ float sm[];
    const uint32_t sbase = smem_u32(sm);
    const int tid  = threadIdx.x;
    const int lane = tid & 31;
    const int w    = tid >> 5;
    const int r4   = lane >> 2;
    const int c4   = lane & 3;
    const int qt   = gridDim.x - 1 - blockIdx.x;   // big tiles first
    const int h    = blockIdx.y;
    const int b    = blockIdx.z;

    const size_t strideT = 3 * CC;
    const float* qg = qkv + (size_t)b * TT * strideT + (size_t)h * HD
                          + (size_t)(qt * 64) * strideT;
    const float* kg = qkv + (size_t)b * TT * strideT + (size_t)h * HD + CC;
    const float* vg = kg + CC;

    auto issue_q = [&]() {
        #pragma unroll
        for (int i = 0; i < 8; i++) {
            int id = tid + i * 128;
            int row = id >> 4, cc = (id & 15) << 2;
            cp_async16(sbase + (uint32_t)(FQ_OFF + row * 68 + cc) * 4u,
                       qg + (size_t)row * strideT + cc);
        }
    };
    auto issue_kv = [&](int j, int buf) {
        const float* kgj = kg + (size_t)(j * 64) * strideT;
        const float* vgj = vg + (size_t)(j * 64) * strideT;
        #pragma unroll
        for (int i = 0; i < 8; i++) {
            int id = tid + i * 128;
            int row = id >> 4, cc = (id & 15) << 2;
            cp_async16(sbase + (uint32_t)(FK_OFF + buf * 4352 + row * 68 + cc) * 4u,
                       kgj + (size_t)row * strideT + cc);
        }
        #pragma unroll
        for (int i = 0; i < 8; i++) {
            int id = tid + i * 128;
            int row = id >> 4, cc = (id & 15) << 2;
            cp_async16(sbase + (uint32_t)(FV_OFF + buf * 4608 + row * 72 + cc) * 4u,
                       vgj + (size_t)row * strideT + cc);
        }
    };

    issue_q();
    issue_kv(0, 0);
    cp_commit();

    uint32_t qa[8][4];
    float o[8][4];
    #pragma unroll
    for (int j2 = 0; j2 < 8; j2++)
        #pragma unroll
        for (int e = 0; e < 4; e++) o[j2][e] = 0.f;
    float m0 = -INFINITY, m1 = -INFINITY, l0 = 0.f, l1 = 0.f;

    for (int j = 0; j <= qt; j++) {
        cp_wait<0>();
        __syncthreads();
        if (j < qt) { issue_kv(j + 1, (j + 1) & 1); cp_commit(); }

        if (j == 0) {
            #pragma unroll
            for (int ks = 0; ks < 8; ks++) {
                const float* p = sm + FQ_OFF + (w * 16 + r4) * 68 + ks * 8 + c4;
                qa[ks][0] = __float_as_uint(p[0]        * 0.125f);
                qa[ks][1] = __float_as_uint(p[8 * 68]   * 0.125f);
                qa[ks][2] = __float_as_uint(p[4]        * 0.125f);
                qa[ks][3] = __float_as_uint(p[8 * 68 + 4] * 0.125f);
            }
        }

        const float* Ksm = sm + FK_OFF + (j & 1) * 4352;
        const float* Vsm = sm + FV_OFF + (j & 1) * 4608;

        float c[8][4];
        #pragma unroll
        for (int j2 = 0; j2 < 8; j2++)
            #pragma unroll
            for (int e = 0; e < 4; e++) c[j2][e] = 0.f;

        #pragma unroll
        for (int ks = 0; ks < 8; ks++) {
            uint32_t bk[8][2];
            #pragma unroll
            for (int j2 = 0; j2 < 8; j2++) {
                const float* p = Ksm + (j2 * 8 + r4) * 68 + ks * 8 + c4;
                bk[j2][0] = __float_as_uint(p[0]);
                bk[j2][1] = __float_as_uint(p[4]);
            }
            #pragma unroll
            for (int j2 = 0; j2 < 8; j2++)
                mma_tf32(c[j2], qa[ks], bk[j2]);
        }

        if (j == qt) {
            const int row0 = w * 16 + r4, row1 = row0 + 8;
            #pragma unroll
            for (int j2 = 0; j2 < 8; j2++) {
                const int col = j2 * 8 + 2 * c4;
                if (col     > row0) c[j2][0] = -INFINITY;
                if (col + 1 > row0) c[j2][1] = -INFINITY;
                if (col     > row1) c[j2][2] = -INFINITY;
                if (col + 1 > row1) c[j2][3] = -INFINITY;
            }
        }

        float mx0 = -INFINITY, mx1 = -INFINITY;
        #pragma unroll
        for (int j2 = 0; j2 < 8; j2++) {
            mx0 = fmaxf(mx0, fmaxf(c[j2][0], c[j2][1]));
            mx1 = fmaxf(mx1, fmaxf(c[j2][2], c[j2][3]));
        }
        mx0 = fmaxf(mx0, __shfl_xor_sync(0xffffffffu, mx0, 1));
        mx0 = fmaxf(mx0, __shfl_xor_sync(0xffffffffu, mx0, 2));
        mx1 = fmaxf(mx1, __shfl_xor_sync(0xffffffffu, mx1, 1));
        mx1 = fmaxf(mx1, __shfl_xor_sync(0xffffffffu, mx1, 2));

        const float mn0 = fmaxf(m0, mx0), mn1 = fmaxf(m1, mx1);
        const float al0 = __expf(m0 - mn0), al1 = __expf(m1 - mn1);
        m0 = mn0; m1 = mn1;

        float ps0 = 0.f, ps1 = 0.f;
        #pragma unroll
        for (int j2 = 0; j2 < 8; j2++) {
            c[j2][0] = __expf(c[j2][0] - mn0);
            c[j2][1] = __expf(c[j2][1] - mn0);
            c[j2][2] = __expf(c[j2][2] - mn1);
            c[j2][3] = __expf(c[j2][3] - mn1);
            ps0 += c[j2][0] + c[j2][1];
            ps1 += c[j2][2] + c[j2][3];
        }
        ps0 += __shfl_xor_sync(0xffffffffu, ps0, 1);
        ps0 += __shfl_xor_sync(0xffffffffu, ps0, 2);
        ps1 += __shfl_xor_sync(0xffffffffu, ps1, 1);
        ps1 += __shfl_xor_sync(0xffffffffu, ps1, 2);
        l0 = l0 * al0 + ps0;
        l1 = l1 * al1 + ps1;

        #pragma unroll
        for (int j2 = 0; j2 < 8; j2++) {
            o[j2][0] *= al0; o[j2][1] *= al0;
            o[j2][2] *= al1; o[j2][3] *= al1;
        }

        #pragma unroll
        for (int j2 = 0; j2 < 8; j2++) {
            *(float2*)(sm + FP_OFF + (w * 16 + r4) * 68 + j2 * 8 + 2 * c4)
                = make_float2(to_tf32(c[j2][0]), to_tf32(c[j2][1]));
            *(float2*)(sm + FP_OFF + (w * 16 + r4 + 8) * 68 + j2 * 8 + 2 * c4)
                = make_float2(to_tf32(c[j2][2]), to_tf32(c[j2][3]));
        }
        __syncwarp();

        #pragma unroll
        for (int ks = 0; ks < 8; ks++) {
            uint32_t pa[4];
            {
                const float* p = sm + FP_OFF + (w * 16 + r4) * 68 + ks * 8 + c4;
                pa[0] = __float_as_uint(p[0]);
                pa[1] = __float_as_uint(p[8 * 68]);
                pa[2] = __float_as_uint(p[4]);
                pa[3] = __float_as_uint(p[8 * 68 + 4]);
            }
            uint32_t bv[8][2];
            #pragma unroll
            for (int j2 = 0; j2 < 8; j2++) {
                const float* p = Vsm + (ks * 8 + c4) * 72 + j2 * 8 + r4;
                bv[j2][0] = __float_as_uint(p[0]);
                bv[j2][1] = __float_as_uint(p[4 * 72]);
            }
            #pragma unroll
            for (int j2 = 0; j2 < 8; j2++)
                mma_tf32(o[j2], pa, bv[j2]);
        }
        __syncwarp();
    }

    const float il0 = 1.f / l0, il1 = 1.f / l1;
    const int gr0 = qt * 64 + w * 16 + r4;
    #pragma unroll
    for (int j2 = 0; j2 < 8; j2++) {
        const int col = h * HD + j2 * 8 + 2 * c4;
        *(float2*)(y + (size_t)((size_t)b * TT + gr0) * CC + col)
            = make_float2(to_tf32(o[j2][0] * il0), to_tf32(o[j2][1] * il0));
        *(float2*)(y + (size_t)((size_t)b * TT + gr0 + 8) * CC + col)
            = make_float2(to_tf32(o[j2][2] * il1), to_tf32(o[j2][3] * il1));
    }
}

// ---------------------------------------------------------------------------
extern "C" void kernel_launch(void* const* d_in, const int* in_sizes, int n_in,
                              void* d_out, int out_size)
{
    const float* x      = (const float*)d_in[0];
    const float* w_attn = (const float*)d_in[1];
    const float* b_attn = (const float*)d_in[2];
    const float* w_proj = (const float*)d_in[3];
    const float* b_proj = (const float*)d_in[4];
    float* out = (float*)d_out;

    float *qkv, *yb, *xr, *war, *wpr;
    cudaGetSymbolAddress((void**)&qkv, g_qkv);
    cudaGetSymbolAddress((void**)&yb,  g_y);
    cudaGetSymbolAddress((void**)&xr,  g_x);
    cudaGetSymbolAddress((void**)&war, g_wa);
    cudaGetSymbolAddress((void**)&wpr, g_wp);

    const int gemmSmem = 3 * STAGE_F * (int)sizeof(float); // 107520
    cudaFuncSetAttribute(gemm_mma, cudaFuncAttributeMaxDynamicSharedMemorySize, gemmSmem);
    cudaFuncSetAttribute(flash_mma, cudaFuncAttributeMaxDynamicSharedMemorySize, FLASH_SMEM_B);

    // tf32(rna) pre-rounding of all GEMM operands, single launch
    round_all<<<1184, 256>>>(x, xr, w_attn, war, w_proj, wpr);

    // 1) qkv = x @ w_attn + b_attn  (tf32 mma; output tf32-rounded for flash)
    gemm_mma<<<dim3(3 * CC / 128, MROWS / 128), 256, gemmSmem>>>(
        xr, war, b_attn, qkv, MROWS, 3 * CC, CC, 1);

    // 2) flash attention (mma.sync tf32) -> g_y (tf32-rounded)
    flash_mma<<<dim3(TT / 64, NH, BB), 128, FLASH_SMEM_B>>>(qkv, yb);

    // 3) out = y @ w_proj + b_proj  (tf32 mma; fp32 output)
    gemm_mma<<<dim3(CC / 128, MROWS / 128), 256, gemmSmem>>>(
        yb, wpr, b_proj, out, MROWS, CC, CC, 0);
}

// round 9
// speedup vs baseline: 1.6133x; 1.6133x over previous
#include <cuda_runtime.h>
#include <cuda_fp16.h>
#include <math.h>
#include <stdint.h>

// Problem dims (fixed by the reference)
#define BB 2
#define TT 2048
#define CC 1024
#define NH 16
#define HD 64
#define MROWS (BB*TT)   // 4096

// Scratch (allocation-free rule: __device__ globals)
__device__ __half g_qk[(size_t)MROWS * 2 * CC];   // Q,K packed [t][2048] half
__device__ __half g_vt[(size_t)CC * MROWS];       // V^T [h*64+d][b*TT+t] half
__device__ __half g_xh[(size_t)MROWS * CC];       // x as half [M][K]
__device__ __half g_waT[(size_t)(3*CC) * CC];     // w_attn^T [3C][C] half
__device__ __half g_wpT[(size_t)CC * CC];         // w_proj^T [C][C] half
__device__ __half g_yh[(size_t)MROWS * CC];       // attention out half [M][C]

// ---------------------------------------------------------------------------
// mma.sync m16n8k16 fp16 -> fp32 accum (sm_80+ path, works on plain sm_100)
__device__ __forceinline__ void mma_f16(float c[4], const uint32_t a[4], const uint32_t b[2]) {
    asm volatile(
        "mma.sync.aligned.m16n8k16.row.col.f32.f16.f16.f32 "
        "{%0,%1,%2,%3}, {%4,%5,%6,%7}, {%8,%9}, {%0,%1,%2,%3};"
        : "+f"(c[0]), "+f"(c[1]), "+f"(c[2]), "+f"(c[3])
        : "r"(a[0]), "r"(a[1]), "r"(a[2]), "r"(a[3]), "r"(b[0]), "r"(b[1]));
}

__device__ __forceinline__ uint32_t smem_u32(const void* p) {
    uint32_t a;
    asm("{ .reg .u64 t; cvta.to.shared.u64 t, %1; cvt.u32.u64 %0, t; }" : "=r"(a) : "l"(p));
    return a;
}
__device__ __forceinline__ void cp_async16(uint32_t dst, const void* src) {
    asm volatile("cp.async.cg.shared.global [%0], [%1], 16;" :: "r"(dst), "l"(src) : "memory");
}
__device__ __forceinline__ void cp_commit() {
    asm volatile("cp.async.commit_group;" ::: "memory");
}
template <int N>
__device__ __forceinline__ void cp_wait() {
    asm volatile("cp.async.wait_group %0;" :: "n"(N) : "memory");
}

// ---------------------------------------------------------------------------
// prep kernels: x -> half; w -> half transposed [N][K]
// ---------------------------------------------------------------------------
__global__ void conv_half(const float* __restrict__ in, __half* __restrict__ out, int n4) {
    int i = blockIdx.x * blockDim.x + threadIdx.x;
    int stride = gridDim.x * blockDim.x;
    for (; i < n4; i += stride) {
        float4 v = ((const float4*)in)[i];
        ((__half2*)out)[2 * i + 0] = __floats2half2_rn(v.x, v.y);
        ((__half2*)out)[2 * i + 1] = __floats2half2_rn(v.z, v.w);
    }
}

// in: fp32 [K][N]; out: half [N][K]. block (32,8), grid (N/32, K/32)
__global__ void transpose_half(const float* __restrict__ in, __half* __restrict__ out,
                               int K, int N) {
    __shared__ float tile[32][33];
    const int n0 = blockIdx.x * 32, k0 = blockIdx.y * 32;
    #pragma unroll
    for (int r = threadIdx.y; r < 32; r += 8)
        tile[r][threadIdx.x] = in[(size_t)(k0 + r) * N + n0 + threadIdx.x];
    __syncthreads();
    #pragma unroll
    for (int r = threadIdx.y; r < 32; r += 8)
        out[(size_t)(n0 + r) * K + k0 + threadIdx.x] = __float2half_rn(tile[threadIdx.x][r]);
}

// ---------------------------------------------------------------------------
// fp16 mma.sync GEMM: C[M,N] = A[M,K] @ Bt[N,K]^T + bias[N]
// CTA 128x128, BK=32 (2 k16 steps), 256 threads (8 warps 2x4), warp 64x32.
// SMEM: per stage A[128][40]h + B[128][40]h = 20480 B; 3 stages = 61440 B.
// mode 0: fp32 out to Cf. mode 1 (QKV): cols<2048 -> half [t][2048] to qkh;
//         cols>=2048 -> transposed half to vt[d][t].
// ---------------------------------------------------------------------------
#define G_LD 40
#define G_STAGE_H 10240   // halves per stage
#define G_BHALF 5120      // B offset within stage (halves)

__global__ __launch_bounds__(256, 2)
void gemm_h(const __half* __restrict__ A, const __half* __restrict__ Bt,
            const float* __restrict__ bias, float* __restrict__ Cf,
            __half* __restrict__ qkh, __half* __restrict__ vt,
            int M, int N, int K, int mode)
{
    extern __shared__ __half smh[];
    const uint32_t sbase = smem_u32(smh);
    const int tid  = threadIdx.x;
    const int lane = tid & 31;
    const int wid  = tid >> 5;
    const int wm   = wid & 1;        // 0..1 (64-row block)
    const int wn   = wid >> 1;       // 0..3 (32-col block)
    const int brow = blockIdx.y, bcol = blockIdx.x;
    const int r4 = lane >> 2, c4 = lane & 3;

    const int NT = K / 32;

    auto issue_stage = [&](int kt, int s) {
        const uint32_t sb = sbase + (uint32_t)s * (G_STAGE_H * 2);
        #pragma unroll
        for (int i = 0; i < 2; i++) {
            int id = tid + i * 256;
            int row = id >> 2, ch = (id & 3) << 3;
            cp_async16(sb + (uint32_t)(row * G_LD + ch) * 2u,
                       A + (size_t)(brow * 128 + row) * K + kt * 32 + ch);
        }
        #pragma unroll
        for (int i = 0; i < 2; i++) {
            int id = tid + i * 256;
            int row = id >> 2, ch = (id & 3) << 3;
            cp_async16(sb + (uint32_t)(G_BHALF + row * G_LD + ch) * 2u,
                       Bt + (size_t)(bcol * 128 + row) * K + kt * 32 + ch);
        }
        cp_commit();
    };

    float acc[4][4][4];
    #pragma unroll
    for (int i = 0; i < 4; i++)
        #pragma unroll
        for (int j = 0; j < 4; j++)
            #pragma unroll
            for (int e = 0; e < 4; e++) acc[i][j][e] = 0.f;

    issue_stage(0, 0);
    issue_stage(1, 1);

    for (int kt = 0; kt < NT; kt++) {
        if (kt + 2 < NT) cp_wait<1>(); else cp_wait<0>();
        __syncthreads();
        if (kt + 2 < NT) issue_stage(kt + 2, (kt + 2) % 3);

        const __half* sA = smh + (kt % 3) * G_STAGE_H;
        const __half* sB = sA + G_BHALF;

        #pragma unroll
        for (int ks = 0; ks < 2; ks++) {
            uint32_t a[4][4], b[4][2];
            #pragma unroll
            for (int i = 0; i < 4; i++) {
                const __half* p = sA + (wm * 64 + i * 16 + r4) * G_LD + ks * 16 + 2 * c4;
                a[i][0] = *(const uint32_t*)p;
                a[i][1] = *(const uint32_t*)(p + 8 * G_LD);
                a[i][2] = *(const uint32_t*)(p + 8);
                a[i][3] = *(const uint32_t*)(p + 8 * G_LD + 8);
            }
            #pragma unroll
            for (int j = 0; j < 4; j++) {
                const __half* p = sB + (wn * 32 + j * 8 + r4) * G_LD + ks * 16 + 2 * c4;
                b[j][0] = *(const uint32_t*)p;
                b[j][1] = *(const uint32_t*)(p + 8);
            }
            #pragma unroll
            for (int i = 0; i < 4; i++)
                #pragma unroll
                for (int j = 0; j < 4; j++)
                    mma_f16(acc[i][j], a[i], b[j]);
        }
        __syncthreads();
    }

    // epilogue
    #pragma unroll
    for (int i = 0; i < 4; i++) {
        const int gm0 = brow * 128 + wm * 64 + i * 16 + r4;
        #pragma unroll
        for (int j = 0; j < 4; j++) {
            const int gn = bcol * 128 + wn * 32 + j * 8 + c4 * 2;
            const float b0 = bias[gn], b1 = bias[gn + 1];
            const float v00 = acc[i][j][0] + b0, v01 = acc[i][j][1] + b1;
            const float v10 = acc[i][j][2] + b0, v11 = acc[i][j][3] + b1;
            if (mode == 0) {
                *(float2*)(Cf + (size_t)gm0 * N + gn)       = make_float2(v00, v01);
                *(float2*)(Cf + (size_t)(gm0 + 8) * N + gn) = make_float2(v10, v11);
            } else if (gn < 2048) {
                *(__half2*)(qkh + (size_t)gm0 * 2048 + gn)       = __floats2half2_rn(v00, v01);
                *(__half2*)(qkh + (size_t)(gm0 + 8) * 2048 + gn) = __floats2half2_rn(v10, v11);
            } else {
                const int d = gn - 2048;
                vt[(size_t)d       * MROWS + gm0]     = __float2half_rn(v00);
                vt[(size_t)(d + 1) * MROWS + gm0]     = __float2half_rn(v01);
                vt[(size_t)d       * MROWS + gm0 + 8] = __float2half_rn(v10);
                vt[(size_t)(d + 1) * MROWS + gm0 + 8] = __float2half_rn(v11);
            }
        }
    }
}

// ---------------------------------------------------------------------------
// Flash attention fp16: mma.sync m16n8k16, fp32 online softmax in frag layout.
// Grid (32, NH, BB), 128 threads (4 warps), warp m16 strip, BKV=64, D=64.
// SMEM (halves, LD=72): Q @0, P @4608, K dbl @9216/@13824, Vt dbl @18432/@23040.
// Total 27648 halves = 55296 B -> 3+ CTAs/SM.
// K tile is [key][d] (natural); V tile is [d][key] (from g_vt) so PV B-frags
// read contiguous key-pairs. All frag LDS are 32-bit, banks 4*r4+c4 (perfect).
// ---------------------------------------------------------------------------
#define FH_Q 0
#define FH_P 4608
#define FH_K 9216
#define FH_V 18432
#define FLASH_SMEM_B (27648 * 2)

__global__ __launch_bounds__(128, 3)
void flash_h(const __half* __restrict__ qkh, const __half* __restrict__ vt,
             __half* __restrict__ y)
{
    extern __shared__ __half smh[];
    const uint32_t sbase = smem_u32(smh);
    const int tid  = threadIdx.x;
    const int lane = tid & 31;
    const int w    = tid >> 5;
    const int r4   = lane >> 2;
    const int c4   = lane & 3;
    const int qt   = gridDim.x - 1 - blockIdx.x;   // big tiles first
    const int h    = blockIdx.y;
    const int b    = blockIdx.z;

    const __half* qg = qkh + (size_t)(b * TT + qt * 64) * 2048 + h * 64;
    const __half* kg = qkh + (size_t)(b * TT) * 2048 + 1024 + h * 64;
    const __half* vg = vt + (size_t)(h * 64) * MROWS + b * TT;

    auto issue_q = [&]() {
        #pragma unroll
        for (int i = 0; i < 4; i++) {
            int id = tid + i * 128;
            int row = id >> 3, ch = (id & 7) << 3;
            cp_async16(sbase + (uint32_t)(FH_Q + row * 72 + ch) * 2u,
                       qg + (size_t)row * 2048 + ch);
        }
    };
    auto issue_kv = [&](int j, int buf) {
        #pragma unroll
        for (int i = 0; i < 4; i++) {
            int id = tid + i * 128;
            int row = id >> 3, ch = (id & 7) << 3;
            cp_async16(sbase + (uint32_t)(FH_K + buf * 4608 + row * 72 + ch) * 2u,
                       kg + (size_t)(j * 64 + row) * 2048 + ch);
        }
        #pragma unroll
        for (int i = 0; i < 4; i++) {
            int id = tid + i * 128;
            int row = id >> 3, ch = (id & 7) << 3;   // row = d, ch = key chunk
            cp_async16(sbase + (uint32_t)(FH_V + buf * 4608 + row * 72 + ch) * 2u,
                       vg + (size_t)row * MROWS + j * 64 + ch);
        }
    };

    issue_q();
    issue_kv(0, 0);
    cp_commit();

    uint32_t qa[4][4];
    float o[8][4];
    #pragma unroll
    for (int j2 = 0; j2 < 8; j2++)
        #pragma unroll
        for (int e = 0; e < 4; e++) o[j2][e] = 0.f;
    float m0 = -INFINITY, m1 = -INFINITY, l0 = 0.f, l1 = 0.f;

    for (int j = 0; j <= qt; j++) {
        cp_wait<0>();
        __syncthreads();
        if (j < qt) { issue_kv(j + 1, (j + 1) & 1); cp_commit(); }

        if (j == 0) {
            #pragma unroll
            for (int ks = 0; ks < 4; ks++) {
                const __half* p = smh + FH_Q + (w * 16 + r4) * 72 + ks * 16 + 2 * c4;
                qa[ks][0] = *(const uint32_t*)p;
                qa[ks][1] = *(const uint32_t*)(p + 8 * 72);
                qa[ks][2] = *(const uint32_t*)(p + 8);
                qa[ks][3] = *(const uint32_t*)(p + 8 * 72 + 8);
            }
        }

        const __half* Ksm = smh + FH_K + (j & 1) * 4608;
        const __half* Vsm = smh + FH_V + (j & 1) * 4608;

        // S = Q @ K^T  (warp: m16 x n64)
        float c[8][4];
        #pragma unroll
        for (int j2 = 0; j2 < 8; j2++)
            #pragma unroll
            for (int e = 0; e < 4; e++) c[j2][e] = 0.f;

        #pragma unroll
        for (int ks = 0; ks < 4; ks++) {
            uint32_t bk[8][2];
            #pragma unroll
            for (int j2 = 0; j2 < 8; j2++) {
                const __half* p = Ksm + (j2 * 8 + r4) * 72 + ks * 16 + 2 * c4;
                bk[j2][0] = *(const uint32_t*)p;
                bk[j2][1] = *(const uint32_t*)(p + 8);
            }
            #pragma unroll
            for (int j2 = 0; j2 < 8; j2++)
                mma_f16(c[j2], qa[ks], bk[j2]);
        }

        // scale, then causal mask on diagonal tile
        #pragma unroll
        for (int j2 = 0; j2 < 8; j2++) {
            c[j2][0] *= 0.125f; c[j2][1] *= 0.125f;
            c[j2][2] *= 0.125f; c[j2][3] *= 0.125f;
        }
        if (j == qt) {
            const int row0 = w * 16 + r4, row1 = row0 + 8;
            #pragma unroll
            for (int j2 = 0; j2 < 8; j2++) {
                const int col = j2 * 8 + 2 * c4;
                if (col     > row0) c[j2][0] = -INFINITY;
                if (col + 1 > row0) c[j2][1] = -INFINITY;
                if (col     > row1) c[j2][2] = -INFINITY;
                if (col + 1 > row1) c[j2][3] = -INFINITY;
            }
        }

        // online softmax (rows r4 / r4+8, quad-reduced)
        float mx0 = -INFINITY, mx1 = -INFINITY;
        #pragma unroll
        for (int j2 = 0; j2 < 8; j2++) {
            mx0 = fmaxf(mx0, fmaxf(c[j2][0], c[j2][1]));
            mx1 = fmaxf(mx1, fmaxf(c[j2][2], c[j2][3]));
        }
        mx0 = fmaxf(mx0, __shfl_xor_sync(0xffffffffu, mx0, 1));
        mx0 = fmaxf(mx0, __shfl_xor_sync(0xffffffffu, mx0, 2));
        mx1 = fmaxf(mx1, __shfl_xor_sync(0xffffffffu, mx1, 1));
        mx1 = fmaxf(mx1, __shfl_xor_sync(0xffffffffu, mx1, 2));

        const float mn0 = fmaxf(m0, mx0), mn1 = fmaxf(m1, mx1);
        const float al0 = __expf(m0 - mn0), al1 = __expf(m1 - mn1);
        m0 = mn0; m1 = mn1;

        float ps0 = 0.f, ps1 = 0.f;
        #pragma unroll
        for (int j2 = 0; j2 < 8; j2++) {
            c[j2][0] = __expf(c[j2][0] - mn0);
            c[j2][1] = __expf(c[j2][1] - mn0);
            c[j2][2] = __expf(c[j2][2] - mn1);
            c[j2][3] = __expf(c[j2][3] - mn1);
            ps0 += c[j2][0] + c[j2][1];
            ps1 += c[j2][2] + c[j2][3];
        }
        ps0 += __shfl_xor_sync(0xffffffffu, ps0, 1);
        ps0 += __shfl_xor_sync(0xffffffffu, ps0, 2);
        ps1 += __shfl_xor_sync(0xffffffffu, ps1, 1);
        ps1 += __shfl_xor_sync(0xffffffffu, ps1, 2);
        l0 = l0 * al0 + ps0;
        l1 = l1 * al1 + ps1;

        #pragma unroll
        for (int j2 = 0; j2 < 8; j2++) {
            o[j2][0] *= al0; o[j2][1] *= al0;
            o[j2][2] *= al1; o[j2][3] *= al1;
        }

        // write P (half) to per-warp smem strip, reload as A-frags
        #pragma unroll
        for (int j2 = 0; j2 < 8; j2++) {
            *(__half2*)(smh + FH_P + (w * 16 + r4) * 72 + j2 * 8 + 2 * c4)
                = __floats2half2_rn(c[j2][0], c[j2][1]);
            *(__half2*)(smh + FH_P + (w * 16 + r4 + 8) * 72 + j2 * 8 + 2 * c4)
                = __floats2half2_rn(c[j2][2], c[j2][3]);
        }
        __syncwarp();

        // O += P @ V
        #pragma unroll
        for (int ks = 0; ks < 4; ks++) {
            uint32_t pa[4];
            {
                const __half* p = smh + FH_P + (w * 16 + r4) * 72 + ks * 16 + 2 * c4;
                pa[0] = *(const uint32_t*)p;
                pa[1] = *(const uint32_t*)(p + 8 * 72);
                pa[2] = *(const uint32_t*)(p + 8);
                pa[3] = *(const uint32_t*)(p + 8 * 72 + 8);
            }
            uint32_t bv[8][2];
            #pragma unroll
            for (int j2 = 0; j2 < 8; j2++) {
                const __half* p = Vsm + (j2 * 8 + r4) * 72 + ks * 16 + 2 * c4;
                bv[j2][0] = *(const uint32_t*)p;
                bv[j2][1] = *(const uint32_t*)(p + 8);
            }
            #pragma unroll
            for (int j2 = 0; j2 < 8; j2++)
                mma_f16(o[j2], pa, bv[j2]);
        }
        __syncwarp();
    }

    // final store (half, feeds proj GEMM)
    const float il0 = 1.f / l0, il1 = 1.f / l1;
    const int gr0 = qt * 64 + w * 16 + r4;
    #pragma unroll
    for (int j2 = 0; j2 < 8; j2++) {
        const int col = h * HD + j2 * 8 + 2 * c4;
        *(__half2*)(y + (size_t)((size_t)b * TT + gr0) * CC + col)
            = __floats2half2_rn(o[j2][0] * il0, o[j2][1] * il0);
        *(__half2*)(y + (size_t)((size_t)b * TT + gr0 + 8) * CC + col)
            = __floats2half2_rn(o[j2][2] * il1, o[j2][3] * il1);
    }
}

// ---------------------------------------------------------------------------
extern "C" void kernel_launch(void* const* d_in, const int* in_sizes, int n_in,
                              void* d_out, int out_size)
{
    const float* x      = (const float*)d_in[0];
    const float* w_attn = (const float*)d_in[1];
    const float* b_attn = (const float*)d_in[2];
    const float* w_proj = (const float*)d_in[3];
    const float* b_proj = (const float*)d_in[4];
    float* out = (float*)d_out;

    __half *qk, *vt, *xh, *waT, *wpT, *yh;
    cudaGetSymbolAddress((void**)&qk,  g_qk);
    cudaGetSymbolAddress((void**)&vt,  g_vt);
    cudaGetSymbolAddress((void**)&xh,  g_xh);
    cudaGetSymbolAddress((void**)&waT, g_waT);
    cudaGetSymbolAddress((void**)&wpT, g_wpT);
    cudaGetSymbolAddress((void**)&yh,  g_yh);

    const int gemmSmem = 3 * G_STAGE_H * 2; // 61440
    cudaFuncSetAttribute(gemm_h, cudaFuncAttributeMaxDynamicSharedMemorySize, gemmSmem);
    cudaFuncSetAttribute(flash_h, cudaFuncAttributeMaxDynamicSharedMemorySize, FLASH_SMEM_B);

    // prep: x -> half, weights -> half transposed
    conv_half<<<512, 256>>>(x, xh, MROWS * CC / 4);
    transpose_half<<<dim3(3 * CC / 32, CC / 32), dim3(32, 8)>>>(w_attn, waT, CC, 3 * CC);
    transpose_half<<<dim3(CC / 32, CC / 32), dim3(32, 8)>>>(w_proj, wpT, CC, CC);

    // 1) qkv = x @ w_attn + b_attn  (fp16 mma; Q,K -> g_qk; V -> g_vt transposed)
    gemm_h<<<dim3(3 * CC / 128, MROWS / 128), 256, gemmSmem>>>(
        xh, waT, b_attn, nullptr, qk, vt, MROWS, 3 * CC, CC, 1);

    // 2) flash attention (fp16 mma) -> g_yh
    flash_h<<<dim3(TT / 64, NH, BB), 128, FLASH_SMEM_B>>>(qk, vt, yh);

    // 3) out = y @ w_proj + b_proj  (fp16 mma; fp32 output)
    gemm_h<<<dim3(CC / 128, MROWS / 128), 256, gemmSmem>>>(
        yh, wpT, b_proj, out, nullptr, nullptr, MROWS, CC, CC, 0);
}

// round 10
// speedup vs baseline: 1.7469x; 1.0828x over previous
#include <cuda_runtime.h>
#include <cuda_fp16.h>
#include <math.h>
#include <stdint.h>

// Problem dims (fixed by the reference)
#define BB 2
#define TT 2048
#define CC 1024
#define NH 16
#define HD 64
#define MROWS (BB*TT)   // 4096

// Scratch (allocation-free rule: __device__ globals)
__device__ __half g_qk[(size_t)MROWS * 2 * CC];   // Q,K packed [t][2048] half
__device__ __half g_vt[(size_t)CC * MROWS];       // V^T [h*64+d][b*TT+t] half
__device__ __half g_xh[(size_t)MROWS * CC];       // x as half [M][K]
__device__ __half g_waT[(size_t)(3*CC) * CC];     // w_attn^T [3C][C] half
__device__ __half g_wpT[(size_t)CC * CC];         // w_proj^T [C][C] half
__device__ __half g_yh[(size_t)MROWS * CC];       // attention out half [M][C]

// ---------------------------------------------------------------------------
// mma.sync m16n8k16 fp16 -> fp32 accum
__device__ __forceinline__ void mma_f16(float c[4], const uint32_t a[4], const uint32_t b[2]) {
    asm volatile(
        "mma.sync.aligned.m16n8k16.row.col.f32.f16.f16.f32 "
        "{%0,%1,%2,%3}, {%4,%5,%6,%7}, {%8,%9}, {%0,%1,%2,%3};"
        : "+f"(c[0]), "+f"(c[1]), "+f"(c[2]), "+f"(c[3])
        : "r"(a[0]), "r"(a[1]), "r"(a[2]), "r"(a[3]), "r"(b[0]), "r"(b[1]));
}

// ldmatrix x4: one instruction loads four 8x8 b16 matrices (A-frag or 2 B-frags)
__device__ __forceinline__ void ldm_x4(uint32_t r[4], uint32_t addr) {
    asm volatile("ldmatrix.sync.aligned.m8n8.x4.shared.b16 {%0,%1,%2,%3}, [%4];"
        : "=r"(r[0]), "=r"(r[1]), "=r"(r[2]), "=r"(r[3]) : "r"(addr));
}

__device__ __forceinline__ uint32_t smem_u32(const void* p) {
    uint32_t a;
    asm("{ .reg .u64 t; cvta.to.shared.u64 t, %1; cvt.u32.u64 %0, t; }" : "=r"(a) : "l"(p));
    return a;
}
__device__ __forceinline__ void cp_async16(uint32_t dst, const void* src) {
    asm volatile("cp.async.cg.shared.global [%0], [%1], 16;" :: "r"(dst), "l"(src) : "memory");
}
__device__ __forceinline__ void cp_commit() {
    asm volatile("cp.async.commit_group;" ::: "memory");
}
template <int N>
__device__ __forceinline__ void cp_wait() {
    asm volatile("cp.async.wait_group %0;" :: "n"(N) : "memory");
}

// ---------------------------------------------------------------------------
// prep kernels: x -> half; w -> half transposed [N][K]
// ---------------------------------------------------------------------------
__global__ void conv_half(const float* __restrict__ in, __half* __restrict__ out, int n4) {
    int i = blockIdx.x * blockDim.x + threadIdx.x;
    int stride = gridDim.x * blockDim.x;
    for (; i < n4; i += stride) {
        float4 v = ((const float4*)in)[i];
        ((__half2*)out)[2 * i + 0] = __floats2half2_rn(v.x, v.y);
        ((__half2*)out)[2 * i + 1] = __floats2half2_rn(v.z, v.w);
    }
}

// in: fp32 [K][N]; out: half [N][K]. block (32,8), grid (N/32, K/32)
__global__ void transpose_half(const float* __restrict__ in, __half* __restrict__ out,
                               int K, int N) {
    __shared__ float tile[32][33];
    const int n0 = blockIdx.x * 32, k0 = blockIdx.y * 32;
    #pragma unroll
    for (int r = threadIdx.y; r < 32; r += 8)
        tile[r][threadIdx.x] = in[(size_t)(k0 + r) * N + n0 + threadIdx.x];
    __syncthreads();
    #pragma unroll
    for (int r = threadIdx.y; r < 32; r += 8)
        out[(size_t)(n0 + r) * K + k0 + threadIdx.x] = __float2half_rn(tile[threadIdx.x][r]);
}

// ---------------------------------------------------------------------------
// fp16 mma.sync GEMM: C[M,N] = A[M,K] @ Bt[N,K]^T + bias[N]
// CTA 128x128, BK=32 (2 k16 steps), 256 threads (8 warps 2x4), warp 64x32.
// SMEM: per stage A[128][40]h + B[128][40]h = 20480 B; 3 stages = 61440 B.
// Fragment loads via ldmatrix.x4 (conflict-free with LD=40 halves).
// mode 0: fp32 out to Cf. mode 1 (QKV): cols<2048 -> half [t][2048] to qkh;
//         cols>=2048 -> transposed half to vt[d][t].
// ---------------------------------------------------------------------------
#define G_LD 40
#define G_STAGE_H 10240   // halves per stage
#define G_BHALF 5120      // B offset within stage (halves)

__global__ __launch_bounds__(256, 2)
void gemm_h(const __half* __restrict__ A, const __half* __restrict__ Bt,
            const float* __restrict__ bias, float* __restrict__ Cf,
            __half* __restrict__ qkh, __half* __restrict__ vt,
            int M, int N, int K, int mode)
{
    extern __shared__ __half smh[];
    const uint32_t sbase = smem_u32(smh);
    const int tid  = threadIdx.x;
    const int lane = tid & 31;
    const int wid  = tid >> 5;
    const int wm   = wid & 1;        // 0..1 (64-row block)
    const int wn   = wid >> 1;       // 0..3 (32-col block)
    const int brow = blockIdx.y, bcol = blockIdx.x;
    const int r4 = lane >> 2, c4 = lane & 3;

    const int NT = K / 32;

    auto issue_stage = [&](int kt, int s) {
        const uint32_t sb = sbase + (uint32_t)s * (G_STAGE_H * 2);
        #pragma unroll
        for (int i = 0; i < 2; i++) {
            int id = tid + i * 256;
            int row = id >> 2, ch = (id & 3) << 3;
            cp_async16(sb + (uint32_t)(row * G_LD + ch) * 2u,
                       A + (size_t)(brow * 128 + row) * K + kt * 32 + ch);
        }
        #pragma unroll
        for (int i = 0; i < 2; i++) {
            int id = tid + i * 256;
            int row = id >> 2, ch = (id & 3) << 3;
            cp_async16(sb + (uint32_t)(G_BHALF + row * G_LD + ch) * 2u,
                       Bt + (size_t)(bcol * 128 + row) * K + kt * 32 + ch);
        }
        cp_commit();
    };

    float acc[4][4][4];
    #pragma unroll
    for (int i = 0; i < 4; i++)
        #pragma unroll
        for (int j = 0; j < 4; j++)
            #pragma unroll
            for (int e = 0; e < 4; e++) acc[i][j][e] = 0.f;

    issue_stage(0, 0);
    issue_stage(1, 1);

    // ldmatrix lane-address components (halves)
    const int lA_row = lane & 15;           // row within 16-row strip
    const int lA_col = (lane >> 4) * 8;     // k-half select
    const int lB_row = (lane & 7) + (lane >> 4) * 8;   // row within 16-n block
    const int lB_col = ((lane >> 3) & 1) * 8;          // k-half select

    for (int kt = 0; kt < NT; kt++) {
        if (kt + 2 < NT) cp_wait<1>(); else cp_wait<0>();
        __syncthreads();
        if (kt + 2 < NT) issue_stage(kt + 2, (kt + 2) % 3);

        const uint32_t sAu = sbase + (uint32_t)((kt % 3) * G_STAGE_H) * 2u;
        const uint32_t sBu = sAu + G_BHALF * 2u;

        #pragma unroll
        for (int ks = 0; ks < 2; ks++) {
            uint32_t a[4][4], b[2][4];
            #pragma unroll
            for (int i = 0; i < 4; i++)
                ldm_x4(a[i], sAu + (uint32_t)((wm * 64 + i * 16 + lA_row) * G_LD
                                              + ks * 16 + lA_col) * 2u);
            #pragma unroll
            for (int jp = 0; jp < 2; jp++)
                ldm_x4(b[jp], sBu + (uint32_t)((wn * 32 + jp * 16 + lB_row) * G_LD
                                               + ks * 16 + lB_col) * 2u);
            #pragma unroll
            for (int i = 0; i < 4; i++)
                #pragma unroll
                for (int jp = 0; jp < 2; jp++) {
                    mma_f16(acc[i][2 * jp],     a[i], &b[jp][0]);
                    mma_f16(acc[i][2 * jp + 1], a[i], &b[jp][2]);
                }
        }
        __syncthreads();
    }

    // epilogue
    #pragma unroll
    for (int i = 0; i < 4; i++) {
        const int gm0 = brow * 128 + wm * 64 + i * 16 + r4;
        #pragma unroll
        for (int j = 0; j < 4; j++) {
            const int gn = bcol * 128 + wn * 32 + j * 8 + c4 * 2;
            const float b0 = bias[gn], b1 = bias[gn + 1];
            const float v00 = acc[i][j][0] + b0, v01 = acc[i][j][1] + b1;
            const float v10 = acc[i][j][2] + b0, v11 = acc[i][j][3] + b1;
            if (mode == 0) {
                *(float2*)(Cf + (size_t)gm0 * N + gn)       = make_float2(v00, v01);
                *(float2*)(Cf + (size_t)(gm0 + 8) * N + gn) = make_float2(v10, v11);
            } else if (gn < 2048) {
                *(__half2*)(qkh + (size_t)gm0 * 2048 + gn)       = __floats2half2_rn(v00, v01);
                *(__half2*)(qkh + (size_t)(gm0 + 8) * 2048 + gn) = __floats2half2_rn(v10, v11);
            } else {
                const int d = gn - 2048;
                vt[(size_t)d       * MROWS + gm0]     = __float2half_rn(v00);
                vt[(size_t)(d + 1) * MROWS + gm0]     = __float2half_rn(v01);
                vt[(size_t)d       * MROWS + gm0 + 8] = __float2half_rn(v10);
                vt[(size_t)(d + 1) * MROWS + gm0 + 8] = __float2half_rn(v11);
            }
        }
    }
}

// ---------------------------------------------------------------------------
// Flash attention fp16: mma.sync m16n8k16 + ldmatrix, fp32 online softmax.
// Grid (32, NH, BB), 128 threads (4 warps), warp m16 strip, BKV=64, D=64.
// SMEM (halves, LD=72): Q @0, P @4608, K dbl @9216/@13824, Vt dbl @18432/@23040.
// Total 27648 halves = 55296 B. K tile [key][d]; V tile [d_out][key] (g_vt).
// ---------------------------------------------------------------------------
#define FH_Q 0
#define FH_P 4608
#define FH_K 9216
#define FH_V 18432
#define FLASH_SMEM_B (27648 * 2)

__global__ __launch_bounds__(128, 3)
void flash_h(const __half* __restrict__ qkh, const __half* __restrict__ vt,
             __half* __restrict__ y)
{
    extern __shared__ __half smh[];
    const uint32_t sbase = smem_u32(smh);
    const int tid  = threadIdx.x;
    const int lane = tid & 31;
    const int w    = tid >> 5;
    const int r4   = lane >> 2;
    const int c4   = lane & 3;
    const int qt   = gridDim.x - 1 - blockIdx.x;   // big tiles first
    const int h    = blockIdx.y;
    const int b    = blockIdx.z;

    const __half* qg = qkh + (size_t)(b * TT + qt * 64) * 2048 + h * 64;
    const __half* kg = qkh + (size_t)(b * TT) * 2048 + 1024 + h * 64;
    const __half* vg = vt + (size_t)(h * 64) * MROWS + b * TT;

    auto issue_q = [&]() {
        #pragma unroll
        for (int i = 0; i < 4; i++) {
            int id = tid + i * 128;
            int row = id >> 3, ch = (id & 7) << 3;
            cp_async16(sbase + (uint32_t)(FH_Q + row * 72 + ch) * 2u,
                       qg + (size_t)row * 2048 + ch);
        }
    };
    auto issue_kv = [&](int j, int buf) {
        #pragma unroll
        for (int i = 0; i < 4; i++) {
            int id = tid + i * 128;
            int row = id >> 3, ch = (id & 7) << 3;
            cp_async16(sbase + (uint32_t)(FH_K + buf * 4608 + row * 72 + ch) * 2u,
                       kg + (size_t)(j * 64 + row) * 2048 + ch);
        }
        #pragma unroll
        for (int i = 0; i < 4; i++) {
            int id = tid + i * 128;
            int row = id >> 3, ch = (id & 7) << 3;   // row = d, ch = key chunk
            cp_async16(sbase + (uint32_t)(FH_V + buf * 4608 + row * 72 + ch) * 2u,
                       vg + (size_t)row * MROWS + j * 64 + ch);
        }
    };

    issue_q();
    issue_kv(0, 0);
    cp_commit();

    // ldmatrix lane-address components (halves)
    const int lA_row = lane & 15;
    const int lA_col = (lane >> 4) * 8;
    const int lB_row = (lane & 7) + (lane >> 4) * 8;
    const int lB_col = ((lane >> 3) & 1) * 8;

    uint32_t qa[4][4];
    float o[8][4];
    #pragma unroll
    for (int j2 = 0; j2 < 8; j2++)
        #pragma unroll
        for (int e = 0; e < 4; e++) o[j2][e] = 0.f;
    float m0 = -INFINITY, m1 = -INFINITY, l0 = 0.f, l1 = 0.f;

    for (int j = 0; j <= qt; j++) {
        cp_wait<0>();
        __syncthreads();
        if (j < qt) { issue_kv(j + 1, (j + 1) & 1); cp_commit(); }

        if (j == 0) {
            #pragma unroll
            for (int ks = 0; ks < 4; ks++)
                ldm_x4(qa[ks], sbase + (uint32_t)(FH_Q + (w * 16 + lA_row) * 72
                                                  + ks * 16 + lA_col) * 2u);
        }

        const uint32_t Ku = sbase + (uint32_t)(FH_K + (j & 1) * 4608) * 2u;
        const uint32_t Vu = sbase + (uint32_t)(FH_V + (j & 1) * 4608) * 2u;
        const uint32_t Pu = sbase + (uint32_t)FH_P * 2u;

        // S = Q @ K^T  (warp: m16 x n64)
        float c[8][4];
        #pragma unroll
        for (int j2 = 0; j2 < 8; j2++)
            #pragma unroll
            for (int e = 0; e < 4; e++) c[j2][e] = 0.f;

        #pragma unroll
        for (int ks = 0; ks < 4; ks++) {
            uint32_t bk[4][4];
            #pragma unroll
            for (int jp = 0; jp < 4; jp++)
                ldm_x4(bk[jp], Ku + (uint32_t)((jp * 16 + lB_row) * 72
                                               + ks * 16 + lB_col) * 2u);
            #pragma unroll
            for (int jp = 0; jp < 4; jp++) {
                mma_f16(c[2 * jp],     qa[ks], &bk[jp][0]);
                mma_f16(c[2 * jp + 1], qa[ks], &bk[jp][2]);
            }
        }

        // scale, then causal mask on diagonal tile
        #pragma unroll
        for (int j2 = 0; j2 < 8; j2++) {
            c[j2][0] *= 0.125f; c[j2][1] *= 0.125f;
            c[j2][2] *= 0.125f; c[j2][3] *= 0.125f;
        }
        if (j == qt) {
            const int row0 = w * 16 + r4, row1 = row0 + 8;
            #pragma unroll
            for (int j2 = 0; j2 < 8; j2++) {
                const int col = j2 * 8 + 2 * c4;
                if (col     > row0) c[j2][0] = -INFINITY;
                if (col + 1 > row0) c[j2][1] = -INFINITY;
                if (col     > row1) c[j2][2] = -INFINITY;
                if (col + 1 > row1) c[j2][3] = -INFINITY;
            }
        }

        // online softmax (rows r4 / r4+8, quad-reduced)
        float mx0 = -INFINITY, mx1 = -INFINITY;
        #pragma unroll
        for (int j2 = 0; j2 < 8; j2++) {
            mx0 = fmaxf(mx0, fmaxf(c[j2][0], c[j2][1]));
            mx1 = fmaxf(mx1, fmaxf(c[j2][2], c[j2][3]));
        }
        mx0 = fmaxf(mx0, __shfl_xor_sync(0xffffffffu, mx0, 1));
        mx0 = fmaxf(mx0, __shfl_xor_sync(0xffffffffu, mx0, 2));
        mx1 = fmaxf(mx1, __shfl_xor_sync(0xffffffffu, mx1, 1));
        mx1 = fmaxf(mx1, __shfl_xor_sync(0xffffffffu, mx1, 2));

        const float mn0 = fmaxf(m0, mx0), mn1 = fmaxf(m1, mx1);
        const float al0 = __expf(m0 - mn0), al1 = __expf(m1 - mn1);
        m0 = mn0; m1 = mn1;

        float ps0 = 0.f, ps1 = 0.f;
        #pragma unroll
        for (int j2 = 0; j2 < 8; j2++) {
            c[j2][0] = __expf(c[j2][0] - mn0);
            c[j2][1] = __expf(c[j2][1] - mn0);
            c[j2][2] = __expf(c[j2][2] - mn1);
            c[j2][3] = __expf(c[j2][3] - mn1);
            ps0 += c[j2][0] + c[j2][1];
            ps1 += c[j2][2] + c[j2][3];
        }
        ps0 += __shfl_xor_sync(0xffffffffu, ps0, 1);
        ps0 += __shfl_xor_sync(0xffffffffu, ps0, 2);
        ps1 += __shfl_xor_sync(0xffffffffu, ps1, 1);
        ps1 += __shfl_xor_sync(0xffffffffu, ps1, 2);
        l0 = l0 * al0 + ps0;
        l1 = l1 * al1 + ps1;

        #pragma unroll
        for (int j2 = 0; j2 < 8; j2++) {
            o[j2][0] *= al0; o[j2][1] *= al0;
            o[j2][2] *= al1; o[j2][3] *= al1;
        }

        // write P (half) to per-warp smem strip, reload as A-frags
        #pragma unroll
        for (int j2 = 0; j2 < 8; j2++) {
            *(__half2*)(smh + FH_P + (w * 16 + r4) * 72 + j2 * 8 + 2 * c4)
                = __floats2half2_rn(c[j2][0], c[j2][1]);
            *(__half2*)(smh + FH_P + (w * 16 + r4 + 8) * 72 + j2 * 8 + 2 * c4)
                = __floats2half2_rn(c[j2][2], c[j2][3]);
        }
        __syncwarp();

        // O += P @ V
        #pragma unroll
        for (int ks = 0; ks < 4; ks++) {
            uint32_t pa[4];
            ldm_x4(pa, Pu + (uint32_t)((w * 16 + lA_row) * 72 + ks * 16 + lA_col) * 2u);
            uint32_t bv[4][4];
            #pragma unroll
            for (int jp = 0; jp < 4; jp++)
                ldm_x4(bv[jp], Vu + (uint32_t)((jp * 16 + lB_row) * 72
                                               + ks * 16 + lB_col) * 2u);
            #pragma unroll
            for (int jp = 0; jp < 4; jp++) {
                mma_f16(o[2 * jp],     pa, &bv[jp][0]);
                mma_f16(o[2 * jp + 1], pa, &bv[jp][2]);
            }
        }
        __syncwarp();
    }

    // final store (half, feeds proj GEMM)
    const float il0 = 1.f / l0, il1 = 1.f / l1;
    const int gr0 = qt * 64 + w * 16 + r4;
    #pragma unroll
    for (int j2 = 0; j2 < 8; j2++) {
        const int col = h * HD + j2 * 8 + 2 * c4;
        *(__half2*)(y + (size_t)((size_t)b * TT + gr0) * CC + col)
            = __floats2half2_rn(o[j2][0] * il0, o[j2][1] * il0);
        *(__half2*)(y + (size_t)((size_t)b * TT + gr0 + 8) * CC + col)
            = __floats2half2_rn(o[j2][2] * il1, o[j2][3] * il1);
    }
}

// ---------------------------------------------------------------------------
extern "C" void kernel_launch(void* const* d_in, const int* in_sizes, int n_in,
                              void* d_out, int out_size)
{
    const float* x      = (const float*)d_in[0];
    const float* w_attn = (const float*)d_in[1];
    const float* b_attn = (const float*)d_in[2];
    const float* w_proj = (const float*)d_in[3];
    const float* b_proj = (const float*)d_in[4];
    float* out = (float*)d_out;

    __half *qk, *vt, *xh, *waT, *wpT, *yh;
    cudaGetSymbolAddress((void**)&qk,  g_qk);
    cudaGetSymbolAddress((void**)&vt,  g_vt);
    cudaGetSymbolAddress((void**)&xh,  g_xh);
    cudaGetSymbolAddress((void**)&waT, g_waT);
    cudaGetSymbolAddress((void**)&wpT, g_wpT);
    cudaGetSymbolAddress((void**)&yh,  g_yh);

    const int gemmSmem = 3 * G_STAGE_H * 2; // 61440
    cudaFuncSetAttribute(gemm_h, cudaFuncAttributeMaxDynamicSharedMemorySize, gemmSmem);
    cudaFuncSetAttribute(flash_h, cudaFuncAttributeMaxDynamicSharedMemorySize, FLASH_SMEM_B);

    // prep: x -> half, weights -> half transposed
    conv_half<<<512, 256>>>(x, xh, MROWS * CC / 4);
    transpose_half<<<dim3(3 * CC / 32, CC / 32), dim3(32, 8)>>>(w_attn, waT, CC, 3 * CC);
    transpose_half<<<dim3(CC / 32, CC / 32), dim3(32, 8)>>>(w_proj, wpT, CC, CC);

    // 1) qkv = x @ w_attn + b_attn  (fp16 mma; Q,K -> g_qk; V -> g_vt transposed)
    gemm_h<<<dim3(3 * CC / 128, MROWS / 128), 256, gemmSmem>>>(
        xh, waT, b_attn, nullptr, qk, vt, MROWS, 3 * CC, CC, 1);

    // 2) flash attention (fp16 mma) -> g_yh
    flash_h<<<dim3(TT / 64, NH, BB), 128, FLASH_SMEM_B>>>(qk, vt, yh);

    // 3) out = y @ w_proj + b_proj  (fp16 mma; fp32 output)
    gemm_h<<<dim3(CC / 128, MROWS / 128), 256, gemmSmem>>>(
        yh, wpT, b_proj, out, nullptr, nullptr, MROWS, CC, CC, 0);
}

// round 11
// speedup vs baseline: 1.8257x; 1.0451x over previous
#include <cuda_runtime.h>
#include <cuda_fp16.h>
#include <math.h>
#include <stdint.h>

// Problem dims (fixed by the reference)
#define BB 2
#define TT 2048
#define CC 1024
#define NH 16
#define HD 64
#define MROWS (BB*TT)   // 4096

// Scratch (allocation-free rule: __device__ globals)
__device__ __half g_qk[(size_t)MROWS * 2 * CC];   // Q,K packed [t][2048] half
__device__ __half g_vt[(size_t)CC * MROWS];       // V^T [h*64+d][b*TT+t] half
__device__ __half g_xh[(size_t)MROWS * CC];       // x as half [M][K]
__device__ __half g_waT[(size_t)(3*CC) * CC];     // w_attn^T [3C][C] half
__device__ __half g_wpT[(size_t)CC * CC];         // w_proj^T [C][C] half
__device__ __half g_yh[(size_t)MROWS * CC];       // attention out half [M][C]

// ---------------------------------------------------------------------------
// mma.sync m16n8k16 fp16 -> fp32 accum
__device__ __forceinline__ void mma_f16(float c[4], const uint32_t a[4], const uint32_t b[2]) {
    asm volatile(
        "mma.sync.aligned.m16n8k16.row.col.f32.f16.f16.f32 "
        "{%0,%1,%2,%3}, {%4,%5,%6,%7}, {%8,%9}, {%0,%1,%2,%3};"
        : "+f"(c[0]), "+f"(c[1]), "+f"(c[2]), "+f"(c[3])
        : "r"(a[0]), "r"(a[1]), "r"(a[2]), "r"(a[3]), "r"(b[0]), "r"(b[1]));
}

// ldmatrix x4: one instruction loads four 8x8 b16 matrices (A-frag or 2 B-frags)
__device__ __forceinline__ void ldm_x4(uint32_t r[4], uint32_t addr) {
    asm volatile("ldmatrix.sync.aligned.m8n8.x4.shared.b16 {%0,%1,%2,%3}, [%4];"
        : "=r"(r[0]), "=r"(r[1]), "=r"(r[2]), "=r"(r[3]) : "r"(addr));
}

__device__ __forceinline__ uint32_t smem_u32(const void* p) {
    uint32_t a;
    asm("{ .reg .u64 t; cvta.to.shared.u64 t, %1; cvt.u32.u64 %0, t; }" : "=r"(a) : "l"(p));
    return a;
}
__device__ __forceinline__ void cp_async16(uint32_t dst, const void* src) {
    asm volatile("cp.async.cg.shared.global [%0], [%1], 16;" :: "r"(dst), "l"(src) : "memory");
}
__device__ __forceinline__ void cp_commit() {
    asm volatile("cp.async.commit_group;" ::: "memory");
}
template <int N>
__device__ __forceinline__ void cp_wait() {
    asm volatile("cp.async.wait_group %0;" :: "n"(N) : "memory");
}

// ---------------------------------------------------------------------------
// prep kernels: x -> half; w -> half transposed [N][K]
// ---------------------------------------------------------------------------
__global__ void conv_half(const float* __restrict__ in, __half* __restrict__ out, int n4) {
    int i = blockIdx.x * blockDim.x + threadIdx.x;
    int stride = gridDim.x * blockDim.x;
    for (; i < n4; i += stride) {
        float4 v = ((const float4*)in)[i];
        ((__half2*)out)[2 * i + 0] = __floats2half2_rn(v.x, v.y);
        ((__half2*)out)[2 * i + 1] = __floats2half2_rn(v.z, v.w);
    }
}

// in: fp32 [K][N]; out: half [N][K]. block (32,8), grid (N/32, K/32)
__global__ void transpose_half(const float* __restrict__ in, __half* __restrict__ out,
                               int K, int N) {
    __shared__ float tile[32][33];
    const int n0 = blockIdx.x * 32, k0 = blockIdx.y * 32;
    #pragma unroll
    for (int r = threadIdx.y; r < 32; r += 8)
        tile[r][threadIdx.x] = in[(size_t)(k0 + r) * N + n0 + threadIdx.x];
    __syncthreads();
    #pragma unroll
    for (int r = threadIdx.y; r < 32; r += 8)
        out[(size_t)(n0 + r) * K + k0 + threadIdx.x] = __float2half_rn(tile[threadIdx.x][r]);
}

// ---------------------------------------------------------------------------
// fp16 mma.sync GEMM v4: C[M,N] = A[M,K] @ Bt[N,K]^T + bias[N]
// CTA 128x128, BK=64 (4 k16 steps per barrier), 256 threads (8 warps 2x4),
// warp tile 64x32. cp.async 3-stage pipeline.
// SMEM: per stage A[128][72]h + B[128][72]h = 36864 B; 3 stages = 110592 B
// -> 2 CTAs/SM (216 KB). LD=72 halves: ldmatrix rows cover banks 0..31
// exactly (36 words/row), conflict-free.
// mode 0: fp32 out to Cf. mode 1 (QKV): cols<2048 -> half [t][2048] to qkh;
//         cols>=2048 -> transposed half to vt[d][t].
// ---------------------------------------------------------------------------
#define G_LD 72
#define G_STAGE_H 18432   // halves per stage
#define G_BHALF 9216      // B offset within stage (halves)
#define G_SMEM_B (3 * G_STAGE_H * 2)   // 110592

__global__ __launch_bounds__(256, 2)
void gemm_h(const __half* __restrict__ A, const __half* __restrict__ Bt,
            const float* __restrict__ bias, float* __restrict__ Cf,
            __half* __restrict__ qkh, __half* __restrict__ vt,
            int M, int N, int K, int mode)
{
    extern __shared__ __half smh[];
    const uint32_t sbase = smem_u32(smh);
    const int tid  = threadIdx.x;
    const int lane = tid & 31;
    const int wid  = tid >> 5;
    const int wm   = wid & 1;        // 0..1 (64-row block)
    const int wn   = wid >> 1;       // 0..3 (32-col block)
    const int brow = blockIdx.y, bcol = blockIdx.x;
    const int r4 = lane >> 2, c4 = lane & 3;

    const int NT = K / 64;

    auto issue_stage = [&](int kt, int s) {
        const uint32_t sb = sbase + (uint32_t)s * (G_STAGE_H * 2);
        #pragma unroll
        for (int i = 0; i < 4; i++) {
            int id = tid + i * 256;
            int row = id >> 3, ch = (id & 7) << 3;   // 64 halves = 8 chunks
            cp_async16(sb + (uint32_t)(row * G_LD + ch) * 2u,
                       A + (size_t)(brow * 128 + row) * K + kt * 64 + ch);
        }
        #pragma unroll
        for (int i = 0; i < 4; i++) {
            int id = tid + i * 256;
            int row = id >> 3, ch = (id & 7) << 3;
            cp_async16(sb + (uint32_t)(G_BHALF + row * G_LD + ch) * 2u,
                       Bt + (size_t)(bcol * 128 + row) * K + kt * 64 + ch);
        }
        cp_commit();
    };

    float acc[4][4][4];
    #pragma unroll
    for (int i = 0; i < 4; i++)
        #pragma unroll
        for (int j = 0; j < 4; j++)
            #pragma unroll
            for (int e = 0; e < 4; e++) acc[i][j][e] = 0.f;

    issue_stage(0, 0);
    issue_stage(1, 1);

    // ldmatrix lane-address components (halves)
    const int lA_row = lane & 15;           // row within 16-row strip
    const int lA_col = (lane >> 4) * 8;     // k-half select
    const int lB_row = (lane & 7) + (lane >> 4) * 8;   // row within 16-n block
    const int lB_col = ((lane >> 3) & 1) * 8;          // k-half select

    for (int kt = 0; kt < NT; kt++) {
        if (kt + 2 < NT) cp_wait<1>(); else cp_wait<0>();
        __syncthreads();
        if (kt + 2 < NT) issue_stage(kt + 2, (kt + 2) % 3);

        const uint32_t sAu = sbase + (uint32_t)((kt % 3) * G_STAGE_H) * 2u;
        const uint32_t sBu = sAu + G_BHALF * 2u;

        #pragma unroll
        for (int ks = 0; ks < 4; ks++) {
            uint32_t a[4][4], b[2][4];
            #pragma unroll
            for (int i = 0; i < 4; i++)
                ldm_x4(a[i], sAu + (uint32_t)((wm * 64 + i * 16 + lA_row) * G_LD
                                              + ks * 16 + lA_col) * 2u);
            #pragma unroll
            for (int jp = 0; jp < 2; jp++)
                ldm_x4(b[jp], sBu + (uint32_t)((wn * 32 + jp * 16 + lB_row) * G_LD
                                               + ks * 16 + lB_col) * 2u);
            #pragma unroll
            for (int i = 0; i < 4; i++)
                #pragma unroll
                for (int jp = 0; jp < 2; jp++) {
                    mma_f16(acc[i][2 * jp],     a[i], &b[jp][0]);
                    mma_f16(acc[i][2 * jp + 1], a[i], &b[jp][2]);
                }
        }
        __syncthreads();
    }

    // epilogue
    #pragma unroll
    for (int i = 0; i < 4; i++) {
        const int gm0 = brow * 128 + wm * 64 + i * 16 + r4;
        #pragma unroll
        for (int j = 0; j < 4; j++) {
            const int gn = bcol * 128 + wn * 32 + j * 8 + c4 * 2;
            const float b0 = bias[gn], b1 = bias[gn + 1];
            const float v00 = acc[i][j][0] + b0, v01 = acc[i][j][1] + b1;
            const float v10 = acc[i][j][2] + b0, v11 = acc[i][j][3] + b1;
            if (mode == 0) {
                *(float2*)(Cf + (size_t)gm0 * N + gn)       = make_float2(v00, v01);
                *(float2*)(Cf + (size_t)(gm0 + 8) * N + gn) = make_float2(v10, v11);
            } else if (gn < 2048) {
                *(__half2*)(qkh + (size_t)gm0 * 2048 + gn)       = __floats2half2_rn(v00, v01);
                *(__half2*)(qkh + (size_t)(gm0 + 8) * 2048 + gn) = __floats2half2_rn(v10, v11);
            } else {
                const int d = gn - 2048;
                vt[(size_t)d       * MROWS + gm0]     = __float2half_rn(v00);
                vt[(size_t)(d + 1) * MROWS + gm0]     = __float2half_rn(v01);
                vt[(size_t)d       * MROWS + gm0 + 8] = __float2half_rn(v10);
                vt[(size_t)(d + 1) * MROWS + gm0 + 8] = __float2half_rn(v11);
            }
        }
    }
}

// ---------------------------------------------------------------------------
// Flash attention fp16: mma.sync m16n8k16 + ldmatrix, fp32 online softmax.
// Grid (32, NH, BB), 128 threads (4 warps), warp m16 strip, BKV=64, D=64.
// SMEM (halves, LD=72): Q @0, P @4608, K dbl @9216/@13824, Vt dbl @18432/@23040.
// Total 27648 halves = 55296 B. K tile [key][d]; V tile [d_out][key] (g_vt).
// ---------------------------------------------------------------------------
#define FH_Q 0
#define FH_P 4608
#define FH_K 9216
#define FH_V 18432
#define FLASH_SMEM_B (27648 * 2)

__global__ __launch_bounds__(128, 3)
void flash_h(const __half* __restrict__ qkh, const __half* __restrict__ vt,
             __half* __restrict__ y)
{
    extern __shared__ __half smh[];
    const uint32_t sbase = smem_u32(smh);
    const int tid  = threadIdx.x;
    const int lane = tid & 31;
    const int w    = tid >> 5;
    const int r4   = lane >> 2;
    const int c4   = lane & 3;
    const int qt   = gridDim.x - 1 - blockIdx.x;   // big tiles first
    const int h    = blockIdx.y;
    const int b    = blockIdx.z;

    const __half* qg = qkh + (size_t)(b * TT + qt * 64) * 2048 + h * 64;
    const __half* kg = qkh + (size_t)(b * TT) * 2048 + 1024 + h * 64;
    const __half* vg = vt + (size_t)(h * 64) * MROWS + b * TT;

    auto issue_q = [&]() {
        #pragma unroll
        for (int i = 0; i < 4; i++) {
            int id = tid + i * 128;
            int row = id >> 3, ch = (id & 7) << 3;
            cp_async16(sbase + (uint32_t)(FH_Q + row * 72 + ch) * 2u,
                       qg + (size_t)row * 2048 + ch);
        }
    };
    auto issue_kv = [&](int j, int buf) {
        #pragma unroll
        for (int i = 0; i < 4; i++) {
            int id = tid + i * 128;
            int row = id >> 3, ch = (id & 7) << 3;
            cp_async16(sbase + (uint32_t)(FH_K + buf * 4608 + row * 72 + ch) * 2u,
                       kg + (size_t)(j * 64 + row) * 2048 + ch);
        }
        #pragma unroll
        for (int i = 0; i < 4; i++) {
            int id = tid + i * 128;
            int row = id >> 3, ch = (id & 7) << 3;   // row = d, ch = key chunk
            cp_async16(sbase + (uint32_t)(FH_V + buf * 4608 + row * 72 + ch) * 2u,
                       vg + (size_t)row * MROWS + j * 64 + ch);
        }
    };

    issue_q();
    issue_kv(0, 0);
    cp_commit();

    // ldmatrix lane-address components (halves)
    const int lA_row = lane & 15;
    const int lA_col = (lane >> 4) * 8;
    const int lB_row = (lane & 7) + (lane >> 4) * 8;
    const int lB_col = ((lane >> 3) & 1) * 8;

    uint32_t qa[4][4];
    float o[8][4];
    #pragma unroll
    for (int j2 = 0; j2 < 8; j2++)
        #pragma unroll
        for (int e = 0; e < 4; e++) o[j2][e] = 0.f;
    float m0 = -INFINITY, m1 = -INFINITY, l0 = 0.f, l1 = 0.f;

    for (int j = 0; j <= qt; j++) {
        cp_wait<0>();
        __syncthreads();
        if (j < qt) { issue_kv(j + 1, (j + 1) & 1); cp_commit(); }

        if (j == 0) {
            #pragma unroll
            for (int ks = 0; ks < 4; ks++)
                ldm_x4(qa[ks], sbase + (uint32_t)(FH_Q + (w * 16 + lA_row) * 72
                                                  + ks * 16 + lA_col) * 2u);
        }

        const uint32_t Ku = sbase + (uint32_t)(FH_K + (j & 1) * 4608) * 2u;
        const uint32_t Vu = sbase + (uint32_t)(FH_V + (j & 1) * 4608) * 2u;
        const uint32_t Pu = sbase + (uint32_t)FH_P * 2u;

        // S = Q @ K^T  (warp: m16 x n64)
        float c[8][4];
        #pragma unroll
        for (int j2 = 0; j2 < 8; j2++)
            #pragma unroll
            for (int e = 0; e < 4; e++) c[j2][e] = 0.f;

        #pragma unroll
        for (int ks = 0; ks < 4; ks++) {
            uint32_t bk[4][4];
            #pragma unroll
            for (int jp = 0; jp < 4; jp++)
                ldm_x4(bk[jp], Ku + (uint32_t)((jp * 16 + lB_row) * 72
                                               + ks * 16 + lB_col) * 2u);
            #pragma unroll
            for (int jp = 0; jp < 4; jp++) {
                mma_f16(c[2 * jp],     qa[ks], &bk[jp][0]);
                mma_f16(c[2 * jp + 1], qa[ks], &bk[jp][2]);
            }
        }

        // scale, then causal mask on diagonal tile
        #pragma unroll
        for (int j2 = 0; j2 < 8; j2++) {
            c[j2][0] *= 0.125f; c[j2][1] *= 0.125f;
            c[j2][2] *= 0.125f; c[j2][3] *= 0.125f;
        }
        if (j == qt) {
            const int row0 = w * 16 + r4, row1 = row0 + 8;
            #pragma unroll
            for (int j2 = 0; j2 < 8; j2++) {
                const int col = j2 * 8 + 2 * c4;
                if (col     > row0) c[j2][0] = -INFINITY;
                if (col + 1 > row0) c[j2][1] = -INFINITY;
                if (col     > row1) c[j2][2] = -INFINITY;
                if (col + 1 > row1) c[j2][3] = -INFINITY;
            }
        }

        // online softmax (rows r4 / r4+8, quad-reduced)
        float mx0 = -INFINITY, mx1 = -INFINITY;
        #pragma unroll
        for (int j2 = 0; j2 < 8; j2++) {
            mx0 = fmaxf(mx0, fmaxf(c[j2][0], c[j2][1]));
            mx1 = fmaxf(mx1, fmaxf(c[j2][2], c[j2][3]));
        }
        mx0 = fmaxf(mx0, __shfl_xor_sync(0xffffffffu, mx0, 1));
        mx0 = fmaxf(mx0, __shfl_xor_sync(0xffffffffu, mx0, 2));
        mx1 = fmaxf(mx1, __shfl_xor_sync(0xffffffffu, mx1, 1));
        mx1 = fmaxf(mx1, __shfl_xor_sync(0xffffffffu, mx1, 2));

        const float mn0 = fmaxf(m0, mx0), mn1 = fmaxf(m1, mx1);
        const float al0 = __expf(m0 - mn0), al1 = __expf(m1 - mn1);
        m0 = mn0; m1 = mn1;

        float ps0 = 0.f, ps1 = 0.f;
        #pragma unroll
        for (int j2 = 0; j2 < 8; j2++) {
            c[j2][0] = __expf(c[j2][0] - mn0);
            c[j2][1] = __expf(c[j2][1] - mn0);
            c[j2][2] = __expf(c[j2][2] - mn1);
            c[j2][3] = __expf(c[j2][3] - mn1);
            ps0 += c[j2][0] + c[j2][1];
            ps1 += c[j2][2] + c[j2][3];
        }
        ps0 += __shfl_xor_sync(0xffffffffu, ps0, 1);
        ps0 += __shfl_xor_sync(0xffffffffu, ps0, 2);
        ps1 += __shfl_xor_sync(0xffffffffu, ps1, 1);
        ps1 += __shfl_xor_sync(0xffffffffu, ps1, 2);
        l0 = l0 * al0 + ps0;
        l1 = l1 * al1 + ps1;

        #pragma unroll
        for (int j2 = 0; j2 < 8; j2++) {
            o[j2][0] *= al0; o[j2][1] *= al0;
            o[j2][2] *= al1; o[j2][3] *= al1;
        }

        // write P (half) to per-warp smem strip, reload as A-frags
        #pragma unroll
        for (int j2 = 0; j2 < 8; j2++) {
            *(__half2*)(smh + FH_P + (w * 16 + r4) * 72 + j2 * 8 + 2 * c4)
                = __floats2half2_rn(c[j2][0], c[j2][1]);
            *(__half2*)(smh + FH_P + (w * 16 + r4 + 8) * 72 + j2 * 8 + 2 * c4)
                = __floats2half2_rn(c[j2][2], c[j2][3]);
        }
        __syncwarp();

        // O += P @ V
        #pragma unroll
        for (int ks = 0; ks < 4; ks++) {
            uint32_t pa[4];
            ldm_x4(pa, Pu + (uint32_t)((w * 16 + lA_row) * 72 + ks * 16 + lA_col) * 2u);
            uint32_t bv[4][4];
            #pragma unroll
            for (int jp = 0; jp < 4; jp++)
                ldm_x4(bv[jp], Vu + (uint32_t)((jp * 16 + lB_row) * 72
                                               + ks * 16 + lB_col) * 2u);
            #pragma unroll
            for (int jp = 0; jp < 4; jp++) {
                mma_f16(o[2 * jp],     pa, &bv[jp][0]);
                mma_f16(o[2 * jp + 1], pa, &bv[jp][2]);
            }
        }
        __syncwarp();
    }

    // final store (half, feeds proj GEMM)
    const float il0 = 1.f / l0, il1 = 1.f / l1;
    const int gr0 = qt * 64 + w * 16 + r4;
    #pragma unroll
    for (int j2 = 0; j2 < 8; j2++) {
        const int col = h * HD + j2 * 8 + 2 * c4;
        *(__half2*)(y + (size_t)((size_t)b * TT + gr0) * CC + col)
            = __floats2half2_rn(o[j2][0] * il0, o[j2][1] * il0);
        *(__half2*)(y + (size_t)((size_t)b * TT + gr0 + 8) * CC + col)
            = __floats2half2_rn(o[j2][2] * il1, o[j2][3] * il1);
    }
}

// ---------------------------------------------------------------------------
extern "C" void kernel_launch(void* const* d_in, const int* in_sizes, int n_in,
                              void* d_out, int out_size)
{
    const float* x      = (const float*)d_in[0];
    const float* w_attn = (const float*)d_in[1];
    const float* b_attn = (const float*)d_in[2];
    const float* w_proj = (const float*)d_in[3];
    const float* b_proj = (const float*)d_in[4];
    float* out = (float*)d_out;

    __half *qk, *vt, *xh, *waT, *wpT, *yh;
    cudaGetSymbolAddress((void**)&qk,  g_qk);
    cudaGetSymbolAddress((void**)&vt,  g_vt);
    cudaGetSymbolAddress((void**)&xh,  g_xh);
    cudaGetSymbolAddress((void**)&waT, g_waT);
    cudaGetSymbolAddress((void**)&wpT, g_wpT);
    cudaGetSymbolAddress((void**)&yh,  g_yh);

    cudaFuncSetAttribute(gemm_h, cudaFuncAttributeMaxDynamicSharedMemorySize, G_SMEM_B);
    cudaFuncSetAttribute(flash_h, cudaFuncAttributeMaxDynamicSharedMemorySize, FLASH_SMEM_B);

    // prep: x -> half, weights -> half transposed
    conv_half<<<512, 256>>>(x, xh, MROWS * CC / 4);
    transpose_half<<<dim3(3 * CC / 32, CC / 32), dim3(32, 8)>>>(w_attn, waT, CC, 3 * CC);
    transpose_half<<<dim3(CC / 32, CC / 32), dim3(32, 8)>>>(w_proj, wpT, CC, CC);

    // 1) qkv = x @ w_attn + b_attn  (fp16 mma; Q,K -> g_qk; V -> g_vt transposed)
    gemm_h<<<dim3(3 * CC / 128, MROWS / 128), 256, G_SMEM_B>>>(
        xh, waT, b_attn, nullptr, qk, vt, MROWS, 3 * CC, CC, 1);

    // 2) flash attention (fp16 mma) -> g_yh
    flash_h<<<dim3(TT / 64, NH, BB), 128, FLASH_SMEM_B>>>(qk, vt, yh);

    // 3) out = y @ w_proj + b_proj  (fp16 mma; fp32 output)
    gemm_h<<<dim3(CC / 128, MROWS / 128), 256, G_SMEM_B>>>(
        yh, wpT, b_proj, out, nullptr, nullptr, MROWS, CC, CC, 0);
}